// round 14
// baseline (speedup 1.0000x reference)
#include <cuda_runtime.h>
#include <cuda_fp16.h>
#include <math.h>

#define NN 50000
#define NE 600000
#define HD 128
#define NG 64
#define HID (NG * 256)
#define SCAN_B 256
#define NBLK ((NN + SCAN_B - 1) / SCAN_B)   // 196

// ---------------- scratch ----------------------------------------------------
__device__ __align__(16) float g_deg[NN];
__device__ __align__(16) float g_self[NN];
__device__ __align__(16) int   g_cnt[NN];
__device__ __align__(16) int   g_ptr[NN + 1];
__device__ __align__(16) int   g_cur[NN];
__device__ __align__(16) int   g_bsum[NBLK];
__device__ __align__(16) int   g_srcA[NE];
__device__ __align__(16) float g_normA[NE];
__device__ __align__(16) __half g_wt[4 * 128 * 128];   // W^T per layer [n][k]
__device__ __align__(16) __half g_t[(size_t)NN * HD];
__device__ __align__(16) __half g_hA[(size_t)NN * HD];
__device__ __align__(16) __half g_hB[(size_t)NN * HD];
__device__ __align__(16) float g_hidden[HID];
__device__ __align__(16) float g_out[NG];
__device__ int g_gs[NG], g_ge[NG];

// ---------------- fused setup: init + x->fp16 + W transpose -----------------
__global__ void k_setup(const float* __restrict__ x, __half* __restrict__ xo,
                        const float* __restrict__ W0, const float* __restrict__ W1,
                        const float* __restrict__ W2, const float* __restrict__ W3) {
    int j = blockIdx.x * blockDim.x + threadIdx.x;
    if (j < NN * HD / 8) {
        float4 v0 = ((const float4*)x)[2 * j];
        float4 v1 = ((const float4*)x)[2 * j + 1];
        __half2 h[4];
        h[0] = __floats2half2_rn(v0.x, v0.y);
        h[1] = __floats2half2_rn(v0.z, v0.w);
        h[2] = __floats2half2_rn(v1.x, v1.y);
        h[3] = __floats2half2_rn(v1.z, v1.w);
        ((uint4*)xo)[j] = *(uint4*)h;
    }
    if (j < NN) { g_deg[j] = 2.0f; g_cnt[j] = 0; }
    if (j < NG) { g_gs[j] = 0; g_ge[j] = 0; }
    if (j < 128 * 128) {
        int k = j >> 7, n = j & 127;
        g_wt[0 * 16384 + n * 128 + k] = __float2half(W0[j]);
        g_wt[1 * 16384 + n * 128 + k] = __float2half(W1[j]);
        g_wt[2 * 16384 + n * 128 + k] = __float2half(W2[j]);
        g_wt[3 * 16384 + n * 128 + k] = __float2half(W3[j]);
    }
}

__global__ void k_deg(const int* __restrict__ ei, const float* __restrict__ ew) {
    int i = blockIdx.x * blockDim.x + threadIdx.x;
    if (i >= NE) return;
    int d = ei[NE + i];
    if ((unsigned)d >= NN) return;
    atomicAdd(&g_deg[d], ew[i]);
    atomicAdd(&g_cnt[d], 1);
}

__global__ void k_bsum() {
    __shared__ int sh[SCAN_B];
    int i = blockIdx.x * SCAN_B + threadIdx.x;
    if (i < NN) {
        float dv = rsqrtf(g_deg[i]);
        g_deg[i] = dv;
        g_self[i] = 2.0f * dv * dv;
    }
    sh[threadIdx.x] = (i < NN) ? g_cnt[i] : 0;
    __syncthreads();
    for (int off = SCAN_B / 2; off > 0; off >>= 1) {
        if (threadIdx.x < off) sh[threadIdx.x] += sh[threadIdx.x + off];
        __syncthreads();
    }
    if (threadIdx.x == 0) g_bsum[blockIdx.x] = sh[0];
}

// row pointers: each block re-scans the 196 block sums, then its own counts.
__global__ void k_ptr(const int* __restrict__ batch) {
    __shared__ int wsum[8];
    __shared__ int sboff;
    const int t = threadIdx.x;

    {
        int bv = (t < NBLK) ? g_bsum[t] : 0;
        int x = bv;
#pragma unroll
        for (int o = 1; o < 32; o <<= 1) {
            int y = __shfl_up_sync(0xffffffffu, x, o);
            if ((t & 31) >= o) x += y;
        }
        if ((t & 31) == 31) wsum[t >> 5] = x;
        __syncthreads();
        if (t < 8) {
            int y = wsum[t];
#pragma unroll
            for (int o = 1; o < 8; o <<= 1) {
                int z = __shfl_up_sync(0xffu, y, o);
                if (t >= o) y += z;
            }
            wsum[t] = y;
        }
        __syncthreads();
        int base = (t >= 32) ? wsum[(t >> 5) - 1] : 0;
        int inc = base + x;
        if (t == blockIdx.x) sboff = inc - bv;
        if (blockIdx.x == 0 && t == NBLK - 1) g_ptr[NN] = inc;
        __syncthreads();
    }

    int i = blockIdx.x * SCAN_B + t;
    int v = (i < NN) ? g_cnt[i] : 0;
    int x = v;
#pragma unroll
    for (int o = 1; o < 32; o <<= 1) {
        int y = __shfl_up_sync(0xffffffffu, x, o);
        if ((t & 31) >= o) x += y;
    }
    if ((t & 31) == 31) wsum[t >> 5] = x;
    __syncthreads();
    if (t < 8) {
        int y = wsum[t];
#pragma unroll
        for (int o = 1; o < 8; o <<= 1) {
            int z = __shfl_up_sync(0xffu, y, o);
            if (t >= o) y += z;
        }
        wsum[t] = y;
    }
    __syncthreads();
    int base = (t >= 32) ? wsum[(t >> 5) - 1] : 0;
    if (i < NN) {
        int p = sboff + base + x - v;
        g_ptr[i] = p;
        g_cur[i] = p;
        int g = batch[i];
        if ((unsigned)g < NG) {
            if (i == 0 || batch[i - 1] != g) g_gs[g] = i;
            if (i == NN - 1 || batch[i + 1] != g) g_ge[g] = i + 1;
        }
    }
}

__global__ void k_scatter(const int* __restrict__ ei, const float* __restrict__ ew) {
    int i = blockIdx.x * blockDim.x + threadIdx.x;
    if (i >= NE) return;
    int s = ei[i];
    int d = ei[NE + i];
    if ((unsigned)s >= NN || (unsigned)d >= NN) return;
    int pos = atomicAdd(&g_cur[d], 1);
    if ((unsigned)pos >= NE) return;
    g_srcA[pos] = s;
    g_normA[pos] = g_deg[s] * ew[i] * g_deg[d];
}

// ---------------- FP16 HMMA GEMM, 4m x 2n warp grid, reg-lean ---------------
#define SK 136
#define GEMM_SMEM (2 * 128 * SK * (int)sizeof(__half))

__device__ __forceinline__ void mma_f16(float* c, unsigned a0, unsigned a1,
                                        unsigned a2, unsigned a3,
                                        unsigned b0, unsigned b1) {
    asm volatile(
        "mma.sync.aligned.m16n8k16.row.col.f32.f16.f16.f32 "
        "{%0,%1,%2,%3}, {%4,%5,%6,%7}, {%8,%9}, {%0,%1,%2,%3};"
        : "+f"(c[0]), "+f"(c[1]), "+f"(c[2]), "+f"(c[3])
        : "r"(a0), "r"(a1), "r"(a2), "r"(a3), "r"(b0), "r"(b1));
}

__device__ __forceinline__ void ldsm_x4(unsigned* r, unsigned addr) {
    asm volatile(
        "ldmatrix.sync.aligned.m8n8.x4.shared.b16 {%0,%1,%2,%3}, [%4];"
        : "=r"(r[0]), "=r"(r[1]), "=r"(r[2]), "=r"(r[3]) : "r"(addr));
}

__global__ __launch_bounds__(256, 3) void k_gemm(const __half* __restrict__ A,
                                                 const __half* __restrict__ Wt,
                                                 __half* __restrict__ O, int nrows) {
    extern __shared__ __half smh[];
    __half* Wn = smh;            // [n][SK]
    __half* As = smh + 128 * SK; // [r][SK]
    const int tid = threadIdx.x;
    const int row0 = blockIdx.x * 128;

#pragma unroll
    for (int i = 0; i < 8; i++) {
        int u = tid + i * 256;
        int n = u >> 4, kq = u & 15;
        *(uint4*)(Wn + n * SK + kq * 8) = *(const uint4*)(Wt + n * 128 + kq * 8);
    }
#pragma unroll
    for (int i = 0; i < 8; i++) {
        int u = tid + i * 256;
        int r = u >> 4, kq = u & 15;
        int gr = row0 + r;
        uint4 v = (gr < nrows) ? *(const uint4*)(A + (size_t)gr * HD + kq * 8)
                               : make_uint4(0u, 0u, 0u, 0u);
        *(uint4*)(As + r * SK + kq * 8) = v;
    }
    __syncthreads();

    const int wid = tid >> 5, lane = tid & 31;
    const int mi = wid & 3;         // 4 M-tiles of 32 rows
    const int ni = wid >> 2;        // 2 N-halves of 64 cols
    const int warpRow = mi * 32;
    const int colBase = ni * 64;
    const int r = lane >> 2;
    const int q = lane & 3;

    unsigned aBase = (unsigned)__cvta_generic_to_shared(
        As + (warpRow + (lane & 15)) * SK + ((lane & 16) ? 8 : 0));
    unsigned bBase = (unsigned)__cvta_generic_to_shared(
        Wn + (colBase + (lane & 7)) * SK + ((lane >> 3) << 3));

    float acc[2][8][4];
#pragma unroll
    for (int rt = 0; rt < 2; rt++)
#pragma unroll
        for (int nt = 0; nt < 8; nt++) {
            acc[rt][nt][0] = 0.f; acc[rt][nt][1] = 0.f;
            acc[rt][nt][2] = 0.f; acc[rt][nt][3] = 0.f;
        }

    // Reg-lean loop: only a[8] + b[4] fragments live at a time (B reloaded
    // per row-tile); target <=85 regs -> 3 blocks/SM -> single wave of 391.
#pragma unroll
    for (int k0 = 0; k0 < 128; k0 += 32) {
#pragma unroll
        for (int rt = 0; rt < 2; rt++) {
            unsigned a[8];
            unsigned ab = aBase + rt * (16 * SK * 2);
            ldsm_x4(a, ab + k0 * 2);
            ldsm_x4(a + 4, ab + (k0 + 16) * 2);
#pragma unroll
            for (int nt = 0; nt < 8; nt++) {
                unsigned b[4];
                ldsm_x4(b, bBase + (nt * 8 * SK + k0) * 2);
                mma_f16(acc[rt][nt], a[0], a[1], a[2], a[3], b[0], b[1]);
                mma_f16(acc[rt][nt], a[4], a[5], a[6], a[7], b[2], b[3]);
            }
        }
    }

#pragma unroll
    for (int rt = 0; rt < 2; rt++) {
        int orowA = row0 + warpRow + rt * 16 + r;
        int orowB = orowA + 8;
#pragma unroll
        for (int nt = 0; nt < 8; nt++) {
            int n = colBase + nt * 8 + q * 2;
            if (orowA < nrows)
                *(__half2*)(O + (size_t)orowA * HD + n) =
                    __floats2half2_rn(acc[rt][nt][0], acc[rt][nt][1]);
            if (orowB < nrows)
                *(__half2*)(O + (size_t)orowB * HD + n) =
                    __floats2half2_rn(acc[rt][nt][2], acc[rt][nt][3]);
        }
    }
}

// ---------------- aggregation: one warp per node, 32-thr blocks -------------
__global__ __launch_bounds__(32) void k_aggr(const __half* __restrict__ T,
                                             const float* __restrict__ bias,
                                             __half* __restrict__ Hout) {
    int gw = blockIdx.x;
    if (gw >= NN) return;
    const int lane = threadIdx.x;
    const int c = lane << 2;

    float sn = g_self[gw];
    uint2 tr = *(const uint2*)(T + (size_t)gw * HD + c);
    float2 ta = __half22float2(*(__half2*)&tr.x);
    float2 tb = __half22float2(*(__half2*)&tr.y);
    float4 acc = make_float4(ta.x * sn, ta.y * sn, tb.x * sn, tb.y * sn);

    int e = g_ptr[gw];
    const int e1 = g_ptr[gw + 1];
    for (; e + 3 < e1; e += 4) {
        int s0 = g_srcA[e], s1 = g_srcA[e + 1], s2 = g_srcA[e + 2], s3 = g_srcA[e + 3];
        float w0 = g_normA[e], w1 = g_normA[e + 1], w2 = g_normA[e + 2], w3 = g_normA[e + 3];
        uint2 r0 = *(const uint2*)(T + (size_t)s0 * HD + c);
        uint2 r1 = *(const uint2*)(T + (size_t)s1 * HD + c);
        uint2 r2 = *(const uint2*)(T + (size_t)s2 * HD + c);
        uint2 r3 = *(const uint2*)(T + (size_t)s3 * HD + c);
        float2 a0 = __half22float2(*(__half2*)&r0.x), b0 = __half22float2(*(__half2*)&r0.y);
        float2 a1 = __half22float2(*(__half2*)&r1.x), b1 = __half22float2(*(__half2*)&r1.y);
        float2 a2 = __half22float2(*(__half2*)&r2.x), b2 = __half22float2(*(__half2*)&r2.y);
        float2 a3 = __half22float2(*(__half2*)&r3.x), b3 = __half22float2(*(__half2*)&r3.y);
        acc.x += w0 * a0.x + w1 * a1.x + w2 * a2.x + w3 * a3.x;
        acc.y += w0 * a0.y + w1 * a1.y + w2 * a2.y + w3 * a3.y;
        acc.z += w0 * b0.x + w1 * b1.x + w2 * b2.x + w3 * b3.x;
        acc.w += w0 * b0.y + w1 * b1.y + w2 * b2.y + w3 * b3.y;
    }
    for (; e < e1; e++) {
        int s = g_srcA[e];
        float w = g_normA[e];
        uint2 rr = *(const uint2*)(T + (size_t)s * HD + c);
        float2 aa = __half22float2(*(__half2*)&rr.x);
        float2 bb2 = __half22float2(*(__half2*)&rr.y);
        acc.x += w * aa.x; acc.y += w * aa.y; acc.z += w * bb2.x; acc.w += w * bb2.y;
    }
    float4 bb = *(const float4*)(bias + c);
    __half2 o[2];
    o[0] = __floats2half2_rn(tanhf(acc.x + bb.x), tanhf(acc.y + bb.y));
    o[1] = __floats2half2_rn(tanhf(acc.z + bb.z), tanhf(acc.w + bb.w));
    *(uint2*)(Hout + (size_t)gw * HD + c) = *(uint2*)o;
}

// ---------------- readout + final dot + direct emit --------------------------
__global__ void k_readout(const __half* __restrict__ Hl, const float* __restrict__ Wout,
                          const float* __restrict__ bout, float* __restrict__ out,
                          int out_size) {
    __shared__ float red[128];
    int g = blockIdx.x;
    int c = threadIdx.x;    // 128
    int s = g_gs[g], e = g_ge[g];
    float vmax = -INFINITY, vsum = 0.0f;
    int i = s;
#pragma unroll 1
    for (; i + 4 <= e; i += 4) {
        float v0 = __half2float(Hl[(size_t)(i + 0) * HD + c]);
        float v1 = __half2float(Hl[(size_t)(i + 1) * HD + c]);
        float v2 = __half2float(Hl[(size_t)(i + 2) * HD + c]);
        float v3 = __half2float(Hl[(size_t)(i + 3) * HD + c]);
        vmax = fmaxf(vmax, fmaxf(fmaxf(v0, v1), fmaxf(v2, v3)));
        vsum += (v0 + v1) + (v2 + v3);
    }
    for (; i < e; i++) {
        float v = __half2float(Hl[(size_t)i * HD + c]);
        vmax = fmaxf(vmax, v);
        vsum += v;
    }
    int cnt = e - s;
    float hmax = (cnt > 0) ? vmax : 0.0f;
    float hmean = vsum / fmaxf((float)cnt, 1.0f);

    g_hidden[(size_t)g * 256 + c] = hmax;
    g_hidden[(size_t)g * 256 + 128 + c] = hmean;
    if (out_size >= NG + HID) {
        out[NG + (size_t)g * 256 + c] = hmax;
        out[NG + (size_t)g * 256 + 128 + c] = hmean;
    }

    red[c] = hmax * Wout[c] + hmean * Wout[128 + c];
    __syncthreads();
    for (int off = 64; off > 0; off >>= 1) {
        if (c < off) red[c] += red[c + off];
        __syncthreads();
    }
    if (c == 0) {
        float r = red[0] + bout[0];
        g_out[g] = r;
        if (out_size >= NG + HID) out[g] = r;
    }
}

__global__ void k_emit(float* __restrict__ out, int out_size) {
    int i = blockIdx.x * blockDim.x + threadIdx.x;
    if (i >= out_size) return;
    float v;
    if (out_size == HID) v = g_hidden[i];
    else v = (i < NG) ? g_out[i] : 0.0f;
    out[i] = v;
}

// ---------------- launch -----------------------------------------------------
extern "C" void kernel_launch(void* const* d_in, const int* in_sizes, int n_in,
                              void* d_out, int out_size) {
    const float* x     = (const float*)d_in[0];
    const int*   ei    = (const int*)d_in[1];
    const int*   batch = (const int*)d_in[2];
    const float* ew    = (const float*)d_in[3];
    const float* W[4] = { (const float*)d_in[4], (const float*)d_in[6],
                          (const float*)d_in[8], (const float*)d_in[10] };
    const float* B[4] = { (const float*)d_in[5], (const float*)d_in[7],
                          (const float*)d_in[9], (const float*)d_in[11] };
    const float* Wout = (const float*)d_in[12];
    const float* bout = (const float*)d_in[13];

    cudaFuncSetAttribute(k_gemm, cudaFuncAttributeMaxDynamicSharedMemorySize, GEMM_SMEM);

    __half *tbuf, *wt, *hA, *hB;
    cudaGetSymbolAddress((void**)&tbuf, g_t);
    cudaGetSymbolAddress((void**)&wt, g_wt);
    cudaGetSymbolAddress((void**)&hA, g_hA);
    cudaGetSymbolAddress((void**)&hB, g_hB);

    const int gemm_grid = (NN + 127) / 128;

    k_setup<<<(NN * HD / 8 + 255) / 256, 256>>>(x, hB, W[0], W[1], W[2], W[3]); // 0
    k_deg<<<(NE + 255) / 256, 256>>>(ei, ew);                                   // 1
    k_bsum<<<NBLK, SCAN_B>>>();                                                 // 2
    k_gemm<<<gemm_grid, 256, GEMM_SMEM>>>(hB, wt, tbuf, NN);                    // 3 <- profiled
    k_ptr<<<NBLK, SCAN_B>>>(batch);                                             // 4
    k_scatter<<<(NE + 255) / 256, 256>>>(ei, ew);                               // 5

    __half* ping[4] = { hA, hB, hA, hB };
    k_aggr<<<NN, 32>>>(tbuf, B[0], ping[0]);
    const __half* cur = ping[0];
    for (int l = 1; l < 4; l++) {
        k_gemm<<<gemm_grid, 256, GEMM_SMEM>>>(cur, wt + l * 16384, tbuf, NN);
        k_aggr<<<NN, 32>>>(tbuf, B[l], ping[l]);
        cur = ping[l];
    }

    k_readout<<<NG, 128>>>(cur, Wout, bout, (float*)d_out, out_size);
    if (out_size < NG + HID)
        k_emit<<<(out_size + 255) / 256, 256>>>((float*)d_out, out_size);
}

// round 15
// speedup vs baseline: 1.3046x; 1.3046x over previous
#include <cuda_runtime.h>
#include <cuda_fp16.h>
#include <math.h>

#define NN 50000
#define NE 600000
#define HD 128
#define NG 64
#define HID (NG * 256)
#define SCAN_B 256
#define NBLK ((NN + SCAN_B - 1) / SCAN_B)   // 196

// ---------------- scratch ----------------------------------------------------
__device__ __align__(16) float g_deg[NN];
__device__ __align__(16) float g_self[NN];
__device__ __align__(16) int   g_cnt[NN];
__device__ __align__(16) int   g_ptr[NN + 1];
__device__ __align__(16) int   g_cur[NN];
__device__ __align__(16) int   g_bsum[NBLK];
__device__ __align__(16) int   g_srcA[NE];
__device__ __align__(16) float g_normA[NE];
__device__ __align__(16) __half g_wt[4 * 128 * 128];   // W^T per layer [n][k]
__device__ __align__(16) __half g_t[(size_t)NN * HD];
__device__ __align__(16) __half g_hA[(size_t)NN * HD];
__device__ __align__(16) __half g_hB[(size_t)NN * HD];
__device__ __align__(16) float g_hidden[HID];
__device__ __align__(16) float g_out[NG];
__device__ int g_gs[NG], g_ge[NG];

// ---------------- fused setup: init + x->fp16 + W transpose -----------------
__global__ void k_setup(const float* __restrict__ x, __half* __restrict__ xo,
                        const float* __restrict__ W0, const float* __restrict__ W1,
                        const float* __restrict__ W2, const float* __restrict__ W3) {
    int j = blockIdx.x * blockDim.x + threadIdx.x;
    if (j < NN * HD / 8) {
        float4 v0 = ((const float4*)x)[2 * j];
        float4 v1 = ((const float4*)x)[2 * j + 1];
        __half2 h[4];
        h[0] = __floats2half2_rn(v0.x, v0.y);
        h[1] = __floats2half2_rn(v0.z, v0.w);
        h[2] = __floats2half2_rn(v1.x, v1.y);
        h[3] = __floats2half2_rn(v1.z, v1.w);
        ((uint4*)xo)[j] = *(uint4*)h;
    }
    if (j < NN) { g_deg[j] = 2.0f; g_cnt[j] = 0; }
    if (j < NG) { g_gs[j] = 0; g_ge[j] = 0; }
    if (j < 128 * 128) {
        int k = j >> 7, n = j & 127;
        g_wt[0 * 16384 + n * 128 + k] = __float2half(W0[j]);
        g_wt[1 * 16384 + n * 128 + k] = __float2half(W1[j]);
        g_wt[2 * 16384 + n * 128 + k] = __float2half(W2[j]);
        g_wt[3 * 16384 + n * 128 + k] = __float2half(W3[j]);
    }
}

__global__ void k_deg(const int* __restrict__ ei, const float* __restrict__ ew) {
    int i = blockIdx.x * blockDim.x + threadIdx.x;
    if (i >= NE) return;
    int d = ei[NE + i];
    if ((unsigned)d >= NN) return;
    atomicAdd(&g_deg[d], ew[i]);
    atomicAdd(&g_cnt[d], 1);
}

__global__ void k_bsum() {
    __shared__ int sh[SCAN_B];
    int i = blockIdx.x * SCAN_B + threadIdx.x;
    if (i < NN) {
        float dv = rsqrtf(g_deg[i]);
        g_deg[i] = dv;
        g_self[i] = 2.0f * dv * dv;
    }
    sh[threadIdx.x] = (i < NN) ? g_cnt[i] : 0;
    __syncthreads();
    for (int off = SCAN_B / 2; off > 0; off >>= 1) {
        if (threadIdx.x < off) sh[threadIdx.x] += sh[threadIdx.x + off];
        __syncthreads();
    }
    if (threadIdx.x == 0) g_bsum[blockIdx.x] = sh[0];
}

// row pointers: each block re-scans the 196 block sums, then its own counts.
__global__ void k_ptr(const int* __restrict__ batch) {
    __shared__ int wsum[8];
    __shared__ int sboff;
    const int t = threadIdx.x;

    {
        int bv = (t < NBLK) ? g_bsum[t] : 0;
        int x = bv;
#pragma unroll
        for (int o = 1; o < 32; o <<= 1) {
            int y = __shfl_up_sync(0xffffffffu, x, o);
            if ((t & 31) >= o) x += y;
        }
        if ((t & 31) == 31) wsum[t >> 5] = x;
        __syncthreads();
        if (t < 8) {
            int y = wsum[t];
#pragma unroll
            for (int o = 1; o < 8; o <<= 1) {
                int z = __shfl_up_sync(0xffu, y, o);
                if (t >= o) y += z;
            }
            wsum[t] = y;
        }
        __syncthreads();
        int base = (t >= 32) ? wsum[(t >> 5) - 1] : 0;
        int inc = base + x;
        if (t == blockIdx.x) sboff = inc - bv;
        if (blockIdx.x == 0 && t == NBLK - 1) g_ptr[NN] = inc;
        __syncthreads();
    }

    int i = blockIdx.x * SCAN_B + t;
    int v = (i < NN) ? g_cnt[i] : 0;
    int x = v;
#pragma unroll
    for (int o = 1; o < 32; o <<= 1) {
        int y = __shfl_up_sync(0xffffffffu, x, o);
        if ((t & 31) >= o) x += y;
    }
    if ((t & 31) == 31) wsum[t >> 5] = x;
    __syncthreads();
    if (t < 8) {
        int y = wsum[t];
#pragma unroll
        for (int o = 1; o < 8; o <<= 1) {
            int z = __shfl_up_sync(0xffu, y, o);
            if (t >= o) y += z;
        }
        wsum[t] = y;
    }
    __syncthreads();
    int base = (t >= 32) ? wsum[(t >> 5) - 1] : 0;
    if (i < NN) {
        int p = sboff + base + x - v;
        g_ptr[i] = p;
        g_cur[i] = p;
        int g = batch[i];
        if ((unsigned)g < NG) {
            if (i == 0 || batch[i - 1] != g) g_gs[g] = i;
            if (i == NN - 1 || batch[i + 1] != g) g_ge[g] = i + 1;
        }
    }
}

__global__ void k_scatter(const int* __restrict__ ei, const float* __restrict__ ew) {
    int i = blockIdx.x * blockDim.x + threadIdx.x;
    if (i >= NE) return;
    int s = ei[i];
    int d = ei[NE + i];
    if ((unsigned)s >= NN || (unsigned)d >= NN) return;
    int pos = atomicAdd(&g_cur[d], 1);
    if ((unsigned)pos >= NE) return;
    g_srcA[pos] = s;
    g_normA[pos] = g_deg[s] * ew[i] * g_deg[d];
}

// ---------------- FP16 HMMA GEMM, 64-row tiles, 2m x 4n warps ---------------
#define SK 136
#define GEMM_SMEM ((128 + 64) * SK * (int)sizeof(__half))   // Wn[128] + As[64]

__device__ __forceinline__ void mma_f16(float* c, unsigned a0, unsigned a1,
                                        unsigned a2, unsigned a3,
                                        unsigned b0, unsigned b1) {
    asm volatile(
        "mma.sync.aligned.m16n8k16.row.col.f32.f16.f16.f32 "
        "{%0,%1,%2,%3}, {%4,%5,%6,%7}, {%8,%9}, {%0,%1,%2,%3};"
        : "+f"(c[0]), "+f"(c[1]), "+f"(c[2]), "+f"(c[3])
        : "r"(a0), "r"(a1), "r"(a2), "r"(a3), "r"(b0), "r"(b1));
}

__device__ __forceinline__ void ldsm_x4(unsigned* r, unsigned addr) {
    asm volatile(
        "ldmatrix.sync.aligned.m8n8.x4.shared.b16 {%0,%1,%2,%3}, [%4];"
        : "=r"(r[0]), "=r"(r[1]), "=r"(r[2]), "=r"(r[3]) : "r"(addr));
}

__global__ __launch_bounds__(256, 3) void k_gemm(const __half* __restrict__ A,
                                                 const __half* __restrict__ Wt,
                                                 __half* __restrict__ O, int nrows) {
    extern __shared__ __half smh[];
    __half* Wn = smh;            // [n=128][SK]
    __half* As = smh + 128 * SK; // [r=64][SK]
    const int tid = threadIdx.x;
    const int row0 = blockIdx.x * 64;

    // Wn fill: 8 uint4/thread
#pragma unroll
    for (int i = 0; i < 8; i++) {
        int u = tid + i * 256;
        int n = u >> 4, kq = u & 15;
        *(uint4*)(Wn + n * SK + kq * 8) = *(const uint4*)(Wt + n * 128 + kq * 8);
    }
    // As fill: 4 uint4/thread
#pragma unroll
    for (int i = 0; i < 4; i++) {
        int u = tid + i * 256;
        int r = u >> 4, kq = u & 15;
        int gr = row0 + r;
        uint4 v = (gr < nrows) ? *(const uint4*)(A + (size_t)gr * HD + kq * 8)
                               : make_uint4(0u, 0u, 0u, 0u);
        *(uint4*)(As + r * SK + kq * 8) = v;
    }
    __syncthreads();

    const int wid = tid >> 5, lane = tid & 31;
    const int mi = wid & 1;         // 2 M-tiles of 32 rows
    const int ni = wid >> 1;        // 4 N-tiles of 32 cols
    const int warpRow = mi * 32;
    const int colBase = ni * 32;
    const int r = lane >> 2;
    const int q = lane & 3;

    unsigned aBase = (unsigned)__cvta_generic_to_shared(
        As + (warpRow + (lane & 15)) * SK + ((lane & 16) ? 8 : 0));
    unsigned bBase = (unsigned)__cvta_generic_to_shared(
        Wn + (colBase + (lane & 7)) * SK + ((lane >> 3) << 3));

    float acc[2][4][4];
#pragma unroll
    for (int rt = 0; rt < 2; rt++)
#pragma unroll
        for (int nt = 0; nt < 4; nt++) {
            acc[rt][nt][0] = 0.f; acc[rt][nt][1] = 0.f;
            acc[rt][nt][2] = 0.f; acc[rt][nt][3] = 0.f;
        }

    // R13-style loop: all A fragments for this k0 held; B shared across rt.
#pragma unroll
    for (int k0 = 0; k0 < 128; k0 += 32) {
        unsigned a[2][8];
        ldsm_x4(a[0], aBase + k0 * 2);
        ldsm_x4(a[0] + 4, aBase + (k0 + 16) * 2);
        ldsm_x4(a[1], aBase + 16 * SK * 2 + k0 * 2);
        ldsm_x4(a[1] + 4, aBase + 16 * SK * 2 + (k0 + 16) * 2);
#pragma unroll
        for (int nt = 0; nt < 4; nt++) {
            unsigned b[4];
            ldsm_x4(b, bBase + (nt * 8 * SK + k0) * 2);
#pragma unroll
            for (int rt = 0; rt < 2; rt++) {
                mma_f16(acc[rt][nt], a[rt][0], a[rt][1], a[rt][2], a[rt][3], b[0], b[1]);
                mma_f16(acc[rt][nt], a[rt][4], a[rt][5], a[rt][6], a[rt][7], b[2], b[3]);
            }
        }
    }

#pragma unroll
    for (int rt = 0; rt < 2; rt++) {
        int orowA = row0 + warpRow + rt * 16 + r;
        int orowB = orowA + 8;
#pragma unroll
        for (int nt = 0; nt < 4; nt++) {
            int n = colBase + nt * 8 + q * 2;
            if (orowA < nrows)
                *(__half2*)(O + (size_t)orowA * HD + n) =
                    __floats2half2_rn(acc[rt][nt][0], acc[rt][nt][1]);
            if (orowB < nrows)
                *(__half2*)(O + (size_t)orowB * HD + n) =
                    __floats2half2_rn(acc[rt][nt][2], acc[rt][nt][3]);
        }
    }
}

// ---------------- aggregation: one warp per destination, 64-thr blocks ------
__global__ __launch_bounds__(64) void k_aggr(const __half* __restrict__ T,
                                             const float* __restrict__ bias,
                                             __half* __restrict__ Hout) {
    int gw = (blockIdx.x * blockDim.x + threadIdx.x) >> 5;
    if (gw >= NN) return;
    const int lane = threadIdx.x & 31;
    const int c = lane << 2;

    float sn = g_self[gw];
    uint2 tr = *(const uint2*)(T + (size_t)gw * HD + c);
    float2 ta = __half22float2(*(__half2*)&tr.x);
    float2 tb = __half22float2(*(__half2*)&tr.y);
    float4 acc = make_float4(ta.x * sn, ta.y * sn, tb.x * sn, tb.y * sn);

    int e = g_ptr[gw];
    const int e1 = g_ptr[gw + 1];
    for (; e + 3 < e1; e += 4) {
        int s0 = g_srcA[e], s1 = g_srcA[e + 1], s2 = g_srcA[e + 2], s3 = g_srcA[e + 3];
        float w0 = g_normA[e], w1 = g_normA[e + 1], w2 = g_normA[e + 2], w3 = g_normA[e + 3];
        uint2 r0 = *(const uint2*)(T + (size_t)s0 * HD + c);
        uint2 r1 = *(const uint2*)(T + (size_t)s1 * HD + c);
        uint2 r2 = *(const uint2*)(T + (size_t)s2 * HD + c);
        uint2 r3 = *(const uint2*)(T + (size_t)s3 * HD + c);
        float2 a0 = __half22float2(*(__half2*)&r0.x), b0 = __half22float2(*(__half2*)&r0.y);
        float2 a1 = __half22float2(*(__half2*)&r1.x), b1 = __half22float2(*(__half2*)&r1.y);
        float2 a2 = __half22float2(*(__half2*)&r2.x), b2 = __half22float2(*(__half2*)&r2.y);
        float2 a3 = __half22float2(*(__half2*)&r3.x), b3 = __half22float2(*(__half2*)&r3.y);
        acc.x += w0 * a0.x + w1 * a1.x + w2 * a2.x + w3 * a3.x;
        acc.y += w0 * a0.y + w1 * a1.y + w2 * a2.y + w3 * a3.y;
        acc.z += w0 * b0.x + w1 * b1.x + w2 * b2.x + w3 * b3.x;
        acc.w += w0 * b0.y + w1 * b1.y + w2 * b2.y + w3 * b3.y;
    }
    for (; e < e1; e++) {
        int s = g_srcA[e];
        float w = g_normA[e];
        uint2 rr = *(const uint2*)(T + (size_t)s * HD + c);
        float2 aa = __half22float2(*(__half2*)&rr.x);
        float2 bb2 = __half22float2(*(__half2*)&rr.y);
        acc.x += w * aa.x; acc.y += w * aa.y; acc.z += w * bb2.x; acc.w += w * bb2.y;
    }
    float4 bb = *(const float4*)(bias + c);
    __half2 o[2];
    o[0] = __floats2half2_rn(tanhf(acc.x + bb.x), tanhf(acc.y + bb.y));
    o[1] = __floats2half2_rn(tanhf(acc.z + bb.z), tanhf(acc.w + bb.w));
    *(uint2*)(Hout + (size_t)gw * HD + c) = *(uint2*)o;
}

// ---------------- readout + final dot + direct emit --------------------------
__global__ void k_readout(const __half* __restrict__ Hl, const float* __restrict__ Wout,
                          const float* __restrict__ bout, float* __restrict__ out,
                          int out_size) {
    __shared__ float red[128];
    int g = blockIdx.x;
    int c = threadIdx.x;    // 128
    int s = g_gs[g], e = g_ge[g];
    float vmax = -INFINITY, vsum = 0.0f;
    int i = s;
#pragma unroll 1
    for (; i + 4 <= e; i += 4) {
        float v0 = __half2float(Hl[(size_t)(i + 0) * HD + c]);
        float v1 = __half2float(Hl[(size_t)(i + 1) * HD + c]);
        float v2 = __half2float(Hl[(size_t)(i + 2) * HD + c]);
        float v3 = __half2float(Hl[(size_t)(i + 3) * HD + c]);
        vmax = fmaxf(vmax, fmaxf(fmaxf(v0, v1), fmaxf(v2, v3)));
        vsum += (v0 + v1) + (v2 + v3);
    }
    for (; i < e; i++) {
        float v = __half2float(Hl[(size_t)i * HD + c]);
        vmax = fmaxf(vmax, v);
        vsum += v;
    }
    int cnt = e - s;
    float hmax = (cnt > 0) ? vmax : 0.0f;
    float hmean = vsum / fmaxf((float)cnt, 1.0f);

    g_hidden[(size_t)g * 256 + c] = hmax;
    g_hidden[(size_t)g * 256 + 128 + c] = hmean;
    if (out_size >= NG + HID) {
        out[NG + (size_t)g * 256 + c] = hmax;
        out[NG + (size_t)g * 256 + 128 + c] = hmean;
    }

    red[c] = hmax * Wout[c] + hmean * Wout[128 + c];
    __syncthreads();
    for (int off = 64; off > 0; off >>= 1) {
        if (c < off) red[c] += red[c + off];
        __syncthreads();
    }
    if (c == 0) {
        float r = red[0] + bout[0];
        g_out[g] = r;
        if (out_size >= NG + HID) out[g] = r;
    }
}

__global__ void k_emit(float* __restrict__ out, int out_size) {
    int i = blockIdx.x * blockDim.x + threadIdx.x;
    if (i >= out_size) return;
    float v;
    if (out_size == HID) v = g_hidden[i];
    else v = (i < NG) ? g_out[i] : 0.0f;
    out[i] = v;
}

// ---------------- launch -----------------------------------------------------
extern "C" void kernel_launch(void* const* d_in, const int* in_sizes, int n_in,
                              void* d_out, int out_size) {
    const float* x     = (const float*)d_in[0];
    const int*   ei    = (const int*)d_in[1];
    const int*   batch = (const int*)d_in[2];
    const float* ew    = (const float*)d_in[3];
    const float* W[4] = { (const float*)d_in[4], (const float*)d_in[6],
                          (const float*)d_in[8], (const float*)d_in[10] };
    const float* B[4] = { (const float*)d_in[5], (const float*)d_in[7],
                          (const float*)d_in[9], (const float*)d_in[11] };
    const float* Wout = (const float*)d_in[12];
    const float* bout = (const float*)d_in[13];

    cudaFuncSetAttribute(k_gemm, cudaFuncAttributeMaxDynamicSharedMemorySize, GEMM_SMEM);

    __half *tbuf, *wt, *hA, *hB;
    cudaGetSymbolAddress((void**)&tbuf, g_t);
    cudaGetSymbolAddress((void**)&wt, g_wt);
    cudaGetSymbolAddress((void**)&hA, g_hA);
    cudaGetSymbolAddress((void**)&hB, g_hB);

    const int gemm_grid = (NN + 63) / 64;      // 782
    const int aggr_grid = (NN * 32 + 63) / 64;

    k_setup<<<(NN * HD / 8 + 255) / 256, 256>>>(x, hB, W[0], W[1], W[2], W[3]); // 0
    k_deg<<<(NE + 255) / 256, 256>>>(ei, ew);                                   // 1
    k_bsum<<<NBLK, SCAN_B>>>();                                                 // 2
    k_gemm<<<gemm_grid, 256, GEMM_SMEM>>>(hB, wt, tbuf, NN);                    // 3 <- profiled
    k_ptr<<<NBLK, SCAN_B>>>(batch);                                             // 4
    k_scatter<<<(NE + 255) / 256, 256>>>(ei, ew);                               // 5

    __half* ping[4] = { hA, hB, hA, hB };
    k_aggr<<<aggr_grid, 64>>>(tbuf, B[0], ping[0]);
    const __half* cur = ping[0];
    for (int l = 1; l < 4; l++) {
        k_gemm<<<gemm_grid, 256, GEMM_SMEM>>>(cur, wt + l * 16384, tbuf, NN);
        k_aggr<<<aggr_grid, 64>>>(tbuf, B[l], ping[l]);
        cur = ping[l];
    }

    k_readout<<<NG, 128>>>(cur, Wout, bout, (float*)d_out, out_size);
    if (out_size < NG + HID)
        k_emit<<<(out_size + 255) / 256, 256>>>((float*)d_out, out_size);
}